// round 6
// baseline (speedup 1.0000x reference)
#include <cuda_runtime.h>

#define ROWS          8192
#define COLS          16384
#define BLOCK         512
#define NWARPS        (BLOCK / 32)       // 16
#define ROWS_PER_CTA  4
#define GRID          (ROWS / ROWS_PER_CTA)   // 2048

// Allocation-free scratch: accumulator + completion counter.
__device__ float    g_acc   = 0.0f;
__device__ unsigned g_count = 0;

// 4 consecutive rows (256 KB contiguous) per CTA. Per row: 8 fully-unrolled
// LDG.128 per thread + warp-shuffle reduce into a per-row smem slot. NO
// barriers between rows; ONE __syncthreads and ONE atomic per CTA.
__global__ void __launch_bounds__(BLOCK) bloss_multirow_kernel(
    const float* __restrict__ B, float* __restrict__ out)
{
    const int lane = threadIdx.x & 31;
    const int wid  = threadIdx.x >> 5;
    const size_t row0 = (size_t)blockIdx.x * ROWS_PER_CTA;

    __shared__ float ws[ROWS_PER_CTA][NWARPS];

    #pragma unroll
    for (int r = 0; r < ROWS_PER_CTA; r++) {
        const float4* __restrict__ p =
            reinterpret_cast<const float4*>(B + (row0 + r) * COLS)
            + threadIdx.x;

        float4 v0 = __ldcs(p);
        float4 v1 = __ldcs(p + 1 * BLOCK);
        float4 v2 = __ldcs(p + 2 * BLOCK);
        float4 v3 = __ldcs(p + 3 * BLOCK);
        float4 v4 = __ldcs(p + 4 * BLOCK);
        float4 v5 = __ldcs(p + 5 * BLOCK);
        float4 v6 = __ldcs(p + 6 * BLOCK);
        float4 v7 = __ldcs(p + 7 * BLOCK);

        float s0 = (v0.x + v0.y) + (v0.z + v0.w);
        float s1 = (v1.x + v1.y) + (v1.z + v1.w);
        float s2 = (v2.x + v2.y) + (v2.z + v2.w);
        float s3 = (v3.x + v3.y) + (v3.z + v3.w);
        float s4 = (v4.x + v4.y) + (v4.z + v4.w);
        float s5 = (v5.x + v5.y) + (v5.z + v5.w);
        float s6 = (v6.x + v6.y) + (v6.z + v6.w);
        float s7 = (v7.x + v7.y) + (v7.z + v7.w);

        float s = ((s0 + s1) + (s2 + s3)) + ((s4 + s5) + (s6 + s7));

        #pragma unroll
        for (int o = 16; o > 0; o >>= 1)
            s += __shfl_down_sync(0xffffffffu, s, o);

        if (lane == 0) ws[r][wid] = s;
        // no barrier: next row's loads issue immediately
    }

    __syncthreads();

    if (threadIdx.x == 0) {
        float acc = 0.0f;
        #pragma unroll
        for (int r = 0; r < ROWS_PER_CTA; r++) {
            float t = ws[r][0];
            #pragma unroll
            for (int w = 1; w < NWARPS; w++) t += ws[r][w];
            acc += fmaxf(t - 1.0f, 0.0f);
        }

        atomicAdd(&g_acc, acc);
        __threadfence();
        unsigned done = atomicAdd(&g_count, 1u);
        if (done == (unsigned)gridDim.x - 1u) {
            float total = *(volatile float*)&g_acc;
            out[0] = total / (float)ROWS;
            // Reset for next graph replay.
            *(volatile float*)&g_acc = 0.0f;
            *(volatile unsigned*)&g_count = 0u;
            __threadfence();
        }
    }
}

// Generic fallback (any cols divisible by 4): one row per CTA.
__global__ void __launch_bounds__(BLOCK) bloss_generic_kernel(
    const float* __restrict__ B, float* __restrict__ out, int cols)
{
    const float4* __restrict__ p =
        reinterpret_cast<const float4*>(B + (size_t)blockIdx.x * (size_t)cols);
    const int n4 = cols >> 2;

    float s0 = 0.0f, s1 = 0.0f, s2 = 0.0f, s3 = 0.0f;
    int i = threadIdx.x;
    for (; i + 3 * BLOCK < n4; i += 4 * BLOCK) {
        float4 v0 = __ldcs(p + i);
        float4 v1 = __ldcs(p + i + BLOCK);
        float4 v2 = __ldcs(p + i + 2 * BLOCK);
        float4 v3 = __ldcs(p + i + 3 * BLOCK);
        s0 += (v0.x + v0.y) + (v0.z + v0.w);
        s1 += (v1.x + v1.y) + (v1.z + v1.w);
        s2 += (v2.x + v2.y) + (v2.z + v2.w);
        s3 += (v3.x + v3.y) + (v3.z + v3.w);
    }
    for (; i < n4; i += BLOCK) {
        float4 v = __ldcs(p + i);
        s0 += (v.x + v.y) + (v.z + v.w);
    }
    float s = (s0 + s1) + (s2 + s3);

    #pragma unroll
    for (int o = 16; o > 0; o >>= 1)
        s += __shfl_down_sync(0xffffffffu, s, o);

    __shared__ float ws[NWARPS];
    if ((threadIdx.x & 31) == 0) ws[threadIdx.x >> 5] = s;
    __syncthreads();

    if (threadIdx.x == 0) {
        float t = ws[0];
        #pragma unroll
        for (int w = 1; w < NWARPS; w++) t += ws[w];
        atomicAdd(&g_acc, fmaxf(t - 1.0f, 0.0f));
        __threadfence();
        unsigned done = atomicAdd(&g_count, 1u);
        if (done == (unsigned)gridDim.x - 1u) {
            float total = *(volatile float*)&g_acc;
            out[0] = total / (float)gridDim.x;
            *(volatile float*)&g_acc = 0.0f;
            *(volatile unsigned*)&g_count = 0u;
            __threadfence();
        }
    }
}

extern "C" void kernel_launch(void* const* d_in, const int* in_sizes, int n_in,
                              void* d_out, int out_size)
{
    const float* B = (const float*)d_in[0];
    const int rows = ROWS;                   // 8192 per problem spec
    const int cols = in_sizes[0] / rows;     // 16384

    if (cols == COLS)
        bloss_multirow_kernel<<<GRID, BLOCK>>>(B, (float*)d_out);
    else
        bloss_generic_kernel<<<rows, BLOCK>>>(B, (float*)d_out, cols);
}

// round 7
// speedup vs baseline: 1.0261x; 1.0261x over previous
#include <cuda_runtime.h>

#define ROWS  8192
#define COLS  16384
#define BLOCK 512
#define NWARPS (BLOCK / 32)

// Allocation-free scratch: accumulator + completion counter.
__device__ float    g_acc   = 0.0f;
__device__ unsigned g_count = 0;

__device__ __forceinline__ void epilogue(float s, float* __restrict__ out,
                                         int nblocks)
{
    // Warp reduce
    #pragma unroll
    for (int o = 16; o > 0; o >>= 1)
        s += __shfl_down_sync(0xffffffffu, s, o);

    __shared__ float ws[NWARPS];
    if ((threadIdx.x & 31) == 0) ws[threadIdx.x >> 5] = s;
    __syncthreads();

    if (threadIdx.x == 0) {
        float t = ws[0];
        #pragma unroll
        for (int w = 1; w < NWARPS; w++) t += ws[w];

        float h = fmaxf(t - 1.0f, 0.0f);
        atomicAdd(&g_acc, h);
        __threadfence();
        unsigned done = atomicAdd(&g_count, 1u);
        if (done == (unsigned)nblocks - 1u) {
            float total = *(volatile float*)&g_acc;
            out[0] = total / (float)nblocks;
            // Reset for next graph replay.
            *(volatile float*)&g_acc = 0.0f;
            *(volatile unsigned*)&g_count = 0u;
            __threadfence();
        }
    }
}

// One CTA per row, 512 threads, each thread loads exactly 8 float4 fully
// unrolled. Single variable vs R5: DEFAULT cache policy (no __ldcs) so LDG.E
// keeps L2_128B promotion on the pure-stream pattern.
__global__ void __launch_bounds__(BLOCK) bloss_unrolled_kernel(
    const float* __restrict__ B, float* __restrict__ out)
{
    const float4* __restrict__ p =
        reinterpret_cast<const float4*>(B + (size_t)blockIdx.x * COLS)
        + threadIdx.x;

    float4 v0 = p[0];
    float4 v1 = p[1 * BLOCK];
    float4 v2 = p[2 * BLOCK];
    float4 v3 = p[3 * BLOCK];
    float4 v4 = p[4 * BLOCK];
    float4 v5 = p[5 * BLOCK];
    float4 v6 = p[6 * BLOCK];
    float4 v7 = p[7 * BLOCK];

    float s0 = (v0.x + v0.y) + (v0.z + v0.w);
    float s1 = (v1.x + v1.y) + (v1.z + v1.w);
    float s2 = (v2.x + v2.y) + (v2.z + v2.w);
    float s3 = (v3.x + v3.y) + (v3.z + v3.w);
    float s4 = (v4.x + v4.y) + (v4.z + v4.w);
    float s5 = (v5.x + v5.y) + (v5.z + v5.w);
    float s6 = (v6.x + v6.y) + (v6.z + v6.w);
    float s7 = (v7.x + v7.y) + (v7.z + v7.w);

    float s = ((s0 + s1) + (s2 + s3)) + ((s4 + s5) + (s6 + s7));
    epilogue(s, out, ROWS);
}

// Generic fallback (any cols divisible by 4): one row per CTA.
__global__ void __launch_bounds__(BLOCK) bloss_generic_kernel(
    const float* __restrict__ B, float* __restrict__ out, int cols)
{
    const float4* __restrict__ p =
        reinterpret_cast<const float4*>(B + (size_t)blockIdx.x * (size_t)cols);
    const int n4 = cols >> 2;

    float s0 = 0.0f, s1 = 0.0f, s2 = 0.0f, s3 = 0.0f;
    int i = threadIdx.x;
    for (; i + 3 * BLOCK < n4; i += 4 * BLOCK) {
        float4 v0 = p[i];
        float4 v1 = p[i + BLOCK];
        float4 v2 = p[i + 2 * BLOCK];
        float4 v3 = p[i + 3 * BLOCK];
        s0 += (v0.x + v0.y) + (v0.z + v0.w);
        s1 += (v1.x + v1.y) + (v1.z + v1.w);
        s2 += (v2.x + v2.y) + (v2.z + v2.w);
        s3 += (v3.x + v3.y) + (v3.z + v3.w);
    }
    for (; i < n4; i += BLOCK) {
        float4 v = p[i];
        s0 += (v.x + v.y) + (v.z + v.w);
    }
    epilogue((s0 + s1) + (s2 + s3), out, ROWS);
}

extern "C" void kernel_launch(void* const* d_in, const int* in_sizes, int n_in,
                              void* d_out, int out_size)
{
    const float* B = (const float*)d_in[0];
    const int rows = ROWS;                   // 8192 per problem spec
    const int cols = in_sizes[0] / rows;     // 16384

    if (cols == COLS)
        bloss_unrolled_kernel<<<rows, BLOCK>>>(B, (float*)d_out);
    else
        bloss_generic_kernel<<<rows, BLOCK>>>(B, (float*)d_out, cols);
}